// round 16
// baseline (speedup 1.0000x reference)
#include <cuda_runtime.h>
#include <cuda_bf16.h>
#include <math.h>

// GLIF recurrence, T=4. Single fused kernel, barrier-free, 256-bit memory ops.
// Grid = 2048 (one block per channel), 256 threads. Threads 0-127 process
// batch 2k, threads 128-255 batch 2k+1; each thread moves 32 B per batch via
// ld/st.global.v8.f32 (sm_100a 256-bit accesses) -> half the LDG/STG and
// address-ALU of the 16B version. 2-deep pair pipeline = 64 B in flight per
// thread (same as best previous config). Params warp-local via shfl.
//
// x: (B=16, PLANE=2048, L=1024) fp32. out: final spike map, fp32 {0,1}.

#define GLIF_T     4
#define GLIF_PLANE 2048
#define GLIF_L     1024
#define GLIF_B     16
#define ROWSTRIDE  (GLIF_PLANE * GLIF_L)   // floats per batch slice (2M)

__device__ __forceinline__ void ldg256(const float* p, float* r) {
    asm volatile("ld.global.v8.f32 {%0,%1,%2,%3,%4,%5,%6,%7}, [%8];"
                 : "=f"(r[0]), "=f"(r[1]), "=f"(r[2]), "=f"(r[3]),
                   "=f"(r[4]), "=f"(r[5]), "=f"(r[6]), "=f"(r[7])
                 : "l"(p));
}
__device__ __forceinline__ void stg256(float* p, const float* r) {
    asm volatile("st.global.v8.f32 [%0], {%1,%2,%3,%4,%5,%6,%7,%8};"
                 :: "l"(p),
                    "f"(r[0]), "f"(r[1]), "f"(r[2]), "f"(r[3]),
                    "f"(r[4]), "f"(r[5]), "f"(r[6]), "f"(r[7])
                 : "memory");
}

__global__ void __launch_bounds__(256) glif_kernel(
    const float* __restrict__ x,
    const float* __restrict__ alpha,
    const float* __restrict__ beta,
    const float* __restrict__ gamma,
    const float* __restrict__ tau,
    const float* __restrict__ Vth,
    const float* __restrict__ leak,
    const float* __restrict__ reVth,
    const float* __restrict__ conduct,
    float* __restrict__ out)
{
    const int c    = blockIdx.x;               // channel
    const int tid  = threadIdx.x;
    const int lane = tid & 31;
    const int pos  = tid & 127;                // position within the row (x8 floats)
    const int bsel = tid >> 7;                 // 0/1: which batch of the pair

    // float-unit offsets, 32-bit (max 33.5M fits)
    const unsigned base = (unsigned)c * GLIF_L + ((unsigned)pos << 3)
                        + (unsigned)bsel * ROWSTRIDE;
    const float* xp = x   + base;
    float*       op = out + base;

    // ---- prefetch pair 0 ----
    float b0[8], b1[8];
    ldg256(xp, b0);

    // ---- warp-local params: lanes 0-7 one sigmoid each, then shfl ----
    const float al = (__ldg(&alpha[c]) > 0.0f) ? 1.0f : 0.0f;  // arch_act(sigmoid)==(p>0)
    const float be = (__ldg(&beta[c])  > 0.0f) ? 1.0f : 0.0f;
    const float ga = (__ldg(&gamma[c]) > 0.0f) ? 1.0f : 0.0f;

    float v = 0.0f;
    if      (lane == 0) v = __ldg(&tau[c]);
    else if (lane == 1) v = __ldg(&Vth[c]);
    else if (lane == 2) v = __ldg(&leak[c]);
    else if (lane == 3) v = __ldg(&reVth[c]);
    else if (lane >= 4 && lane < 8) v = __ldg(&conduct[(lane - 4) * GLIF_PLANE + c]);

    const float sig = 1.0f / (1.0f + expf(-v));

    float r = sig;                                              // lane 1: vth
    if      (lane == 0) r = 1.0f - al * (1.0f - sig);           // A
    else if (lane == 2) r = -((1.0f - al) * sig);               // negLk
    else if (lane == 3) r = -((1.0f - ga) * sig);               // negR
    else if (lane >= 4 && lane < 8) r = 1.0f - be * (1.0f - sig);  // s_t

    const float A     = __shfl_sync(0xffffffffu, r, 0);
    const float vth   = __shfl_sync(0xffffffffu, r, 1);
    const float negLk = __shfl_sync(0xffffffffu, r, 2);
    const float negR  = __shfl_sync(0xffffffffu, r, 3);
    const float s0    = __shfl_sync(0xffffffffu, r, 4);
    float sv[3];
    sv[0] = __shfl_sync(0xffffffffu, r, 5);
    sv[1] = __shfl_sync(0xffffffffu, r, 6);
    sv[2] = __shfl_sync(0xffffffffu, r, 7);
    const float omg = 1.0f - ga;

    // ---- 8 pair-iterations (16 batches), 2-deep pipeline ----
#pragma unroll
    for (int i = 0; i < GLIF_B / 2; ++i) {
        float* cur = (i & 1) ? b1 : b0;
        float* nxt = (i & 1) ? b0 : b1;
        if (i + 1 < GLIF_B / 2)
            ldg256(xp + (unsigned)(i + 1) * (2u * ROWSTRIDE), nxt);

        float res[8];
#pragma unroll
        for (int j = 0; j < 8; ++j) {
            const float xj = cur[j];
            // t=0: u=0, o=0 -> u1 = x*s0 - Lk
            float uu = fmaf(xj, s0, negLk);
            bool  o  = (uu > vth);
#pragma unroll
            for (int t = 0; t < 3; ++t) {
                // reference order: ((A*u)*(1-ga*o) - Lk) + x*s - R*o
                const float g = o ? omg : 1.0f;
                float m = (A * uu) * g;
                m = m + negLk;
                m = fmaf(xj, sv[t], m);
                if (o) m = m + negR;
                o = (m > vth);
                uu = m;
            }
            res[j] = o ? 1.0f : 0.0f;
        }
        stg256(op + (unsigned)i * (2u * ROWSTRIDE), res);
    }
}

extern "C" void kernel_launch(void* const* d_in, const int* in_sizes, int n_in,
                              void* d_out, int out_size) {
    const float* x       = (const float*)d_in[0];
    const float* alpha   = (const float*)d_in[1];
    const float* beta    = (const float*)d_in[2];
    const float* gamma   = (const float*)d_in[3];
    const float* tau     = (const float*)d_in[4];
    const float* Vth     = (const float*)d_in[5];
    const float* leak    = (const float*)d_in[6];
    const float* reVth   = (const float*)d_in[7];
    const float* conduct = (const float*)d_in[8];
    float* out = (float*)d_out;

    glif_kernel<<<GLIF_PLANE, 256>>>(x, alpha, beta, gamma, tau, Vth,
                                     leak, reVth, conduct, out);
}

// round 17
// speedup vs baseline: 1.0006x; 1.0006x over previous
#include <cuda_runtime.h>
#include <cuda_bf16.h>
#include <math.h>

// GLIF recurrence, T=4. Single fused kernel, barrier-free, finest granularity.
// Grid = 8192: block = (channel, quarter); each block streams 4 batches of one
// channel (16 KiB R + 16 KiB W). All 4 loads issued up-front (MLP=4 from
// instruction 0), then warp-local params (lanes 0-7 one sigmoid each,
// broadcast via shfl — no smem, no __syncthreads), then compute + 4 stores.
//
// x: (B=16, PLANE=2048, L=1024) fp32. out: final spike map, fp32 {0,1}.

#define GLIF_T        4
#define GLIF_PLANE    2048
#define GLIF_L        1024
#define GLIF_B        16
#define BATCH_PER_BLK 4

__global__ void __launch_bounds__(256) glif_kernel(
    const float* __restrict__ x,
    const float* __restrict__ alpha,
    const float* __restrict__ beta,
    const float* __restrict__ gamma,
    const float* __restrict__ tau,
    const float* __restrict__ Vth,
    const float* __restrict__ leak,
    const float* __restrict__ reVth,
    const float* __restrict__ conduct,
    float* __restrict__ out)
{
    const int c    = blockIdx.x >> 2;          // channel
    const int quad = blockIdx.x & 3;           // batches [quad*4, quad*4+4)
    const int tid  = threadIdx.x;
    const int lane = tid & 31;

    const unsigned row4  = GLIF_PLANE * (GLIF_L / 4);    // float4 per batch
    const unsigned base4 = (unsigned)(quad * BATCH_PER_BLK) * row4
                         + (unsigned)c * (GLIF_L / 4) + tid;
    const float4* xp = reinterpret_cast<const float4*>(x) + base4;
    float4*       op = reinterpret_cast<float4*>(out) + base4;

    // ---- all 4 loads up-front: MLP=4 from the first instruction ----
    float4 xv[4];
#pragma unroll
    for (int u = 0; u < 4; ++u)
        xv[u] = __ldcs(xp + u * row4);

    // ---- warp-local params: lanes 0-7 one sigmoid each, then shfl ----
    const float al = (__ldg(&alpha[c]) > 0.0f) ? 1.0f : 0.0f;  // arch_act(sigmoid)==(p>0)
    const float be = (__ldg(&beta[c])  > 0.0f) ? 1.0f : 0.0f;
    const float ga = (__ldg(&gamma[c]) > 0.0f) ? 1.0f : 0.0f;

    float v = 0.0f;
    if      (lane == 0) v = __ldg(&tau[c]);
    else if (lane == 1) v = __ldg(&Vth[c]);
    else if (lane == 2) v = __ldg(&leak[c]);
    else if (lane == 3) v = __ldg(&reVth[c]);
    else if (lane >= 4 && lane < 8) v = __ldg(&conduct[(lane - 4) * GLIF_PLANE + c]);

    const float sig = 1.0f / (1.0f + expf(-v));

    float r = sig;                                              // lane 1: vth
    if      (lane == 0) r = 1.0f - al * (1.0f - sig);           // A
    else if (lane == 2) r = -((1.0f - al) * sig);               // negLk
    else if (lane == 3) r = -((1.0f - ga) * sig);               // negR
    else if (lane >= 4 && lane < 8) r = 1.0f - be * (1.0f - sig);  // s_t

    const float A     = __shfl_sync(0xffffffffu, r, 0);
    const float vth   = __shfl_sync(0xffffffffu, r, 1);
    const float negLk = __shfl_sync(0xffffffffu, r, 2);
    const float negR  = __shfl_sync(0xffffffffu, r, 3);
    const float s0    = __shfl_sync(0xffffffffu, r, 4);
    float sv[3];
    sv[0] = __shfl_sync(0xffffffffu, r, 5);
    sv[1] = __shfl_sync(0xffffffffu, r, 6);
    sv[2] = __shfl_sync(0xffffffffu, r, 7);
    const float omg = 1.0f - ga;

    // ---- compute + store the 4 batches ----
#pragma unroll
    for (int u = 0; u < 4; ++u) {
        const float4 xq = xv[u];
        float xl[4] = {xq.x, xq.y, xq.z, xq.w};
        float ov[4];
#pragma unroll
        for (int j = 0; j < 4; ++j) {
            const float xj = xl[j];
            // t=0: u=0, o=0 -> u1 = x*s0 - Lk
            float uu = fmaf(xj, s0, negLk);
            bool  o  = (uu > vth);
#pragma unroll
            for (int t = 0; t < 3; ++t) {
                // reference order: ((A*u)*(1-ga*o) - Lk) + x*s - R*o
                const float g = o ? omg : 1.0f;
                float m = (A * uu) * g;
                m = m + negLk;
                m = fmaf(xj, sv[t], m);
                if (o) m = m + negR;
                o = (m > vth);
                uu = m;
            }
            ov[j] = o ? 1.0f : 0.0f;
        }
        float4 res;
        res.x = ov[0]; res.y = ov[1]; res.z = ov[2]; res.w = ov[3];
        __stcs(op + u * row4, res);
    }
}

extern "C" void kernel_launch(void* const* d_in, const int* in_sizes, int n_in,
                              void* d_out, int out_size) {
    const float* x       = (const float*)d_in[0];
    const float* alpha   = (const float*)d_in[1];
    const float* beta    = (const float*)d_in[2];
    const float* gamma   = (const float*)d_in[3];
    const float* tau     = (const float*)d_in[4];
    const float* Vth     = (const float*)d_in[5];
    const float* leak    = (const float*)d_in[6];
    const float* reVth   = (const float*)d_in[7];
    const float* conduct = (const float*)d_in[8];
    float* out = (float*)d_out;

    const int n_blk = out_size / (GLIF_L * BATCH_PER_BLK);   // 8192
    glif_kernel<<<n_blk, 256>>>(x, alpha, beta, gamma, tau, Vth,
                                leak, reVth, conduct, out);
}